// round 3
// baseline (speedup 1.0000x reference)
#include <cuda_runtime.h>
#include <cuda_bf16.h>
#include <cstdint>

#define B_ 16
#define N_ 8732
#define C_ 81
#define TOPK_ 200
#define CONF_ 0.01f
#define NMS_ 0.45f

// Scratch (device globals: no allocation allowed)
__device__ float  g_probsT[B_ * C_ * N_];   // [B, C, N] softmax probs, transposed
__device__ float4 g_boxes [B_ * N_];        // [B, N] decoded xyxy

// ---------------------------------------------------------------------------
// Bitwise replica of libdevice __nv_expf (CUDA math library algorithm).
// Immune to -use_fast_math demotion and FMA contraction ambiguity.
// ---------------------------------------------------------------------------
__device__ __forceinline__ float exp_rn(float a) {
    float f, r, j, s, t;
    int i, ia;
    // i = rint(a / log(2)) via round-to-nearest-even shift trick
    j = fmaf(1.442695f, a, 12582912.f);
    j = __fsub_rn(j, 12582912.f);
    f = fmaf(j, -6.93145752e-1f, a);   // log(2)_hi
    f = fmaf(j, -1.42860677e-6f, f);   // log(2)_lo
    i = (int)j;
    // polynomial approx of exp(f) on [-log(2)/2, +log(2)/2]
    r =         1.37805939e-3f;
    r = fmaf(r, f, 8.37312452e-3f);
    r = fmaf(r, f, 4.16695364e-2f);
    r = fmaf(r, f, 1.66664720e-1f);
    r = fmaf(r, f, 4.99999851e-1f);
    r = fmaf(r, f, 1.00000000e+0f);
    r = fmaf(r, f, 1.00000000e+0f);
    // scale by 2**i, split to avoid overflow in the scale factor
    ia = (i > 0) ? 0 : 0x83000000;
    s = __int_as_float(0x7f000000 + ia);
    t = __int_as_float((i << 23) - ia);
    r = __fmul_rn(r, s);
    r = __fmul_rn(r, t);
    // severe overflow/underflow (never hit by this workload's ranges)
    if (fabsf(a) >= 104.0f) {
        r = (a > 0.0f) ? __int_as_float(0x7f800000) : 0.0f;
    }
    return r;
}

// ---------------------------------------------------------------------------
// Kernel 1: softmax over C=81 per (b,n) row, write transposed [B,C,N]
// ---------------------------------------------------------------------------
__global__ __launch_bounds__(1024) void softmax_T_kernel(const float* __restrict__ conf) {
    __shared__ float tile[32][81];   // stride 81: gcd(81,32)=1 -> conflict-free
    int b    = blockIdx.y;
    int n0   = blockIdx.x * 32;
    int warp = threadIdx.x >> 5;
    int lane = threadIdx.x & 31;
    int n    = n0 + warp;

    if (n < N_) {
        const float* row = conf + ((size_t)(b * N_ + n)) * C_;
        float v0 = row[lane];
        float v1 = (lane + 32 < C_) ? row[lane + 32] : -1e30f;
        float v2 = (lane + 64 < C_) ? row[lane + 64] : -1e30f;
        float m = fmaxf(v0, fmaxf(v1, v2));
        #pragma unroll
        for (int o = 16; o; o >>= 1) m = fmaxf(m, __shfl_xor_sync(0xFFFFFFFFu, m, o));
        float e0 = exp_rn(__fsub_rn(v0, m));
        float e1 = (lane + 32 < C_) ? exp_rn(__fsub_rn(v1, m)) : 0.0f;
        float e2 = (lane + 64 < C_) ? exp_rn(__fsub_rn(v2, m)) : 0.0f;
        float s = __fadd_rn(__fadd_rn(e0, e1), e2);
        #pragma unroll
        for (int o = 16; o; o >>= 1) s = __fadd_rn(s, __shfl_xor_sync(0xFFFFFFFFu, s, o));
        tile[warp][lane] = __fdiv_rn(e0, s);
        if (lane + 32 < C_) tile[warp][lane + 32] = __fdiv_rn(e1, s);
        if (lane + 64 < C_) tile[warp][lane + 64] = __fdiv_rn(e2, s);
    }
    __syncthreads();

    // coalesced transposed write: consecutive threads -> consecutive n
    for (int idx = threadIdx.x; idx < 32 * C_; idx += 1024) {
        int c  = idx >> 5;
        int nn = idx & 31;
        int ng = n0 + nn;
        if (ng < N_)
            g_probsT[((size_t)b * C_ + c) * N_ + ng] = tile[nn][c];
    }
}

// ---------------------------------------------------------------------------
// Kernel 2: decode boxes. Bitwise-exact vs reference:
//   cxcy = a_xy + (loc_xy * 0.1) * a_wh      (separate mul, mul, add)
//   wh   = a_wh * exp(loc_wh * 0.2)
//   out  = [cxcy - wh*0.5, cxcy + wh*0.5]
// All ops via _rn intrinsics: no FMA contraction, no fast-math demotion.
// ---------------------------------------------------------------------------
__global__ void decode_kernel(const float* __restrict__ loc,
                              const float* __restrict__ anchors) {
    int i = blockIdx.x * blockDim.x + threadIdx.x;
    if (i >= B_ * N_) return;
    int n = i % N_;
    float4 l = ((const float4*)loc)[i];
    float4 a = ((const float4*)anchors)[n];
    float cx = __fadd_rn(a.x, __fmul_rn(__fmul_rn(l.x, 0.1f), a.z));
    float cy = __fadd_rn(a.y, __fmul_rn(__fmul_rn(l.y, 0.1f), a.w));
    float w  = __fmul_rn(a.z, exp_rn(__fmul_rn(l.z, 0.2f)));
    float h  = __fmul_rn(a.w, exp_rn(__fmul_rn(l.w, 0.2f)));
    float hw = __fmul_rn(w, 0.5f);
    float hh = __fmul_rn(h, 0.5f);
    g_boxes[i] = make_float4(__fsub_rn(cx, hw), __fsub_rn(cy, hh),
                             __fadd_rn(cx, hw), __fadd_rn(cy, hh));
}

// ---------------------------------------------------------------------------
// Kernel 3: per-(b, class!=0) top-200 + IoU + sequential NMS + output
// ---------------------------------------------------------------------------
__global__ __launch_bounds__(256) void nms_kernel(float* __restrict__ out) {
    __shared__ unsigned long long cand[2048];                 // 16 KB (aliases hist)
    __shared__ unsigned spart[256];
    __shared__ float4   sbox [TOPK_];
    __shared__ float    svals[TOPK_];
    __shared__ float    sarea[TOPK_];
    __shared__ unsigned smask[TOPK_ * 7];                     // iou>thr bits, j>i
    __shared__ unsigned skeep[7];
    __shared__ int      sBstar, sSub, sCount, sNeed2, sCntGt;

    unsigned* hist = (unsigned*)cand;   // 2048 bins

    int task = blockIdx.x;
    int b    = task / (C_ - 1);
    int cls  = task % (C_ - 1) + 1;
    int t    = threadIdx.x;

    const float* prow = g_probsT + ((size_t)b * C_ + cls) * N_;

    // --- 1. histogram of top-11 float bits (all probs >= 0) ---
    for (int i = t; i < 2048; i += 256) hist[i] = 0;
    __syncthreads();
    for (int n = t; n < N_; n += 256) {
        unsigned bits = __float_as_uint(prow[n]);
        atomicAdd(&hist[bits >> 20], 1u);
    }
    __syncthreads();

    // --- 2. find cutoff bin B*: count(bins >= B*) >= 200 ---
    {
        unsigned s = 0;
        #pragma unroll
        for (int q = 0; q < 8; q++) s += hist[t * 8 + q];
        spart[t] = s;
    }
    __syncthreads();
    if (t == 0) {
        int acc = 0, seg = 0;
        for (int u = 255; u >= 0; u--) {
            if (acc + (int)spart[u] >= TOPK_) { seg = u; break; }
            acc += (int)spart[u];
        }
        int cgt = acc, bstar = seg * 8, bcnt = 0;
        for (int bin = seg * 8 + 7; bin >= seg * 8; bin--) {
            int h = (int)hist[bin];
            if (cgt + h >= TOPK_) { bstar = bin; bcnt = h; break; }
            cgt += h;
        }
        sBstar = bstar;
        sCntGt = cgt;
        sNeed2 = (cgt + bcnt > 2040);
        sSub   = 0;
        sCount = 0;
        #pragma unroll
        for (int w = 0; w < 7; w++) skeep[w] = 0;
    }
    __syncthreads();

    unsigned bstar = (unsigned)sBstar;

    // --- 2b. optional refinement: sub-histogram on bits[19:9] within bin B* ---
    if (sNeed2) {
        for (int i = t; i < 2048; i += 256) hist[i] = 0;
        __syncthreads();
        for (int n = t; n < N_; n += 256) {
            unsigned bits = __float_as_uint(prow[n]);
            if ((bits >> 20) == bstar)
                atomicAdd(&hist[(bits >> 9) & 0x7FF], 1u);
        }
        __syncthreads();
        {
            unsigned s = 0;
            #pragma unroll
            for (int q = 0; q < 8; q++) s += hist[t * 8 + q];
            spart[t] = s;
        }
        __syncthreads();
        if (t == 0) {
            int need = TOPK_ - sCntGt;
            int acc = 0, seg = 0;
            for (int u = 255; u >= 0; u--) {
                if (acc + (int)spart[u] >= need) { seg = u; break; }
                acc += (int)spart[u];
            }
            int sb = seg * 8;
            for (int bin = seg * 8 + 7; bin >= seg * 8; bin--) {
                int h = (int)hist[bin];
                if (acc + h >= need) { sb = bin; break; }
                acc += h;
            }
            sSub = sb;
        }
        __syncthreads();
    }
    unsigned subcut = (unsigned)sSub;

    // --- 3. collect candidates; key = valbits<<32 | ~index (desc val, asc idx) ---
    for (int n = t; n < N_; n += 256) {
        unsigned bits = __float_as_uint(prow[n]);
        unsigned bin = bits >> 20;
        if (bin > bstar || (bin == bstar && ((bits >> 9) & 0x7FF) >= subcut)) {
            int p = atomicAdd(&sCount, 1);
            if (p < 2048)
                cand[p] = ((unsigned long long)bits << 32) | (unsigned)(0xFFFFFFFFu - (unsigned)n);
        }
    }
    __syncthreads();

    int M = sCount; if (M > 2048) M = 2048;
    int NP = 256; while (NP < M) NP <<= 1;
    for (int i = t; i < NP; i += 256) if (i >= M) cand[i] = 0ull;
    __syncthreads();

    // --- 4. bitonic sort descending ---
    for (int k = 2; k <= NP; k <<= 1) {
        for (int j = k >> 1; j > 0; j >>= 1) {
            for (int i = t; i < NP; i += 256) {
                int ixj = i ^ j;
                if (ixj > i) {
                    unsigned long long a = cand[i], bb = cand[ixj];
                    bool desc = ((i & k) == 0);
                    if (desc ? (a < bb) : (a > bb)) { cand[i] = bb; cand[ixj] = a; }
                }
            }
            __syncthreads();
        }
    }

    // --- 5. gather top-200 boxes, init keep bits (val > thresh) ---
    if (t < TOPK_) {
        unsigned long long key = cand[t];
        float v = __uint_as_float((unsigned)(key >> 32));
        unsigned n = 0xFFFFFFFFu - (unsigned)key;
        svals[t] = v;
        float4 bx = g_boxes[(size_t)b * N_ + n];
        sbox[t] = bx;
        sarea[t] = __fmul_rn(__fsub_rn(bx.z, bx.x), __fsub_rn(bx.w, bx.y));
        if (v > CONF_) atomicOr(&skeep[t >> 5], 1u << (t & 31));
    }
    __syncthreads();

    // --- 6. suppression bitmask (exact ref arithmetic, no FMA contraction) ---
    for (int unit = t; unit < TOPK_ * 7; unit += 256) {
        int i = unit / 7, w = unit % 7;
        float4 bi = sbox[i];
        float  ai = sarea[i];
        unsigned word = 0;
        int j0 = w * 32;
        #pragma unroll 4
        for (int jj = 0; jj < 32; jj++) {
            int j = j0 + jj;
            if (j < TOPK_ && j > i) {
                float4 bj = sbox[j];
                float lx = fmaxf(bi.x, bj.x), ly = fmaxf(bi.y, bj.y);
                float rx = fminf(bi.z, bj.z), ry = fminf(bi.w, bj.w);
                float iw = fmaxf(__fsub_rn(rx, lx), 0.0f);
                float ih = fmaxf(__fsub_rn(ry, ly), 0.0f);
                float inter = __fmul_rn(iw, ih);
                float uni = __fsub_rn(__fadd_rn(ai, sarea[j]), inter);
                float iou = __fdiv_rn(inter, fmaxf(uni, 1e-12f));
                if (iou > NMS_) word |= (1u << jj);
            }
        }
        smask[i * 7 + w] = word;
    }
    __syncthreads();

    // --- 7. sequential NMS (exact scan semantics) ---
    if (t == 0) {
        for (int i = 0; i < TOPK_; i++) {
            if (skeep[i >> 5] & (1u << (i & 31))) {
                #pragma unroll
                for (int w = 0; w < 7; w++) skeep[w] &= ~smask[i * 7 + w];
            }
        }
    }
    __syncthreads();

    // --- 8. write [200,5] rows: (score, x1,y1,x2,y2), zeroed if suppressed ---
    if (t < TOPK_) {
        bool kp = (skeep[t >> 5] >> (t & 31)) & 1u;
        float* o = out + (((size_t)b * C_ + cls) * TOPK_ + t) * 5;
        float4 bx = sbox[t];
        o[0] = kp ? svals[t] : 0.0f;
        o[1] = kp ? bx.x : 0.0f;
        o[2] = kp ? bx.y : 0.0f;
        o[3] = kp ? bx.z : 0.0f;
        o[4] = kp ? bx.w : 0.0f;
    }
}

// ---------------------------------------------------------------------------
extern "C" void kernel_launch(void* const* d_in, const int* in_sizes, int n_in,
                              void* d_out, int out_size) {
    const float* loc     = (const float*)d_in[0];   // [B,N,4]
    const float* conf    = (const float*)d_in[1];   // [B,N,C]
    const float* anchors = (const float*)d_in[2];   // [N,4]
    float* out = (float*)d_out;                     // [B,C,200,5]

    cudaMemsetAsync(out, 0, (size_t)out_size * sizeof(float), 0);

    dim3 g1((N_ + 31) / 32, B_);
    softmax_T_kernel<<<g1, 1024>>>(conf);

    int tot = B_ * N_;
    decode_kernel<<<(tot + 255) / 256, 256>>>(loc, anchors);

    nms_kernel<<<B_ * (C_ - 1), 256>>>(out);
}

// round 4
// speedup vs baseline: 1.1648x; 1.1648x over previous
#include <cuda_runtime.h>
#include <cuda_bf16.h>
#include <cstdint>

#define B_ 16
#define N_ 8732
#define C_ 81
#define NV4_ 2183            // N_/4, exact
#define TOPK_ 200
#define CONF_ 0.01f
#define NMS_ 0.45f

__device__ float  g_probsT[B_ * C_ * N_];   // [B, C, N] softmax probs, transposed
__device__ float4 g_boxes [B_ * N_];        // [B, N] decoded xyxy

// ---------------------------------------------------------------------------
// Bitwise replica of libdevice __nv_expf — immune to fast-math / contraction.
// ---------------------------------------------------------------------------
__device__ __forceinline__ float exp_rn(float a) {
    float f, r, j, s, t;
    int i, ia;
    j = fmaf(1.442695f, a, 12582912.f);
    j = __fsub_rn(j, 12582912.f);
    f = fmaf(j, -6.93145752e-1f, a);
    f = fmaf(j, -1.42860677e-6f, f);
    i = (int)j;
    r =         1.37805939e-3f;
    r = fmaf(r, f, 8.37312452e-3f);
    r = fmaf(r, f, 4.16695364e-2f);
    r = fmaf(r, f, 1.66664720e-1f);
    r = fmaf(r, f, 4.99999851e-1f);
    r = fmaf(r, f, 1.00000000e+0f);
    r = fmaf(r, f, 1.00000000e+0f);
    ia = (i > 0) ? 0 : 0x83000000;
    s = __int_as_float(0x7f000000 + ia);
    t = __int_as_float((i << 23) - ia);
    r = __fmul_rn(r, s);
    r = __fmul_rn(r, t);
    if (fabsf(a) >= 104.0f) r = (a > 0.0f) ? __int_as_float(0x7f800000) : 0.0f;
    return r;
}

// ---------------------------------------------------------------------------
// Kernel 1: softmax over C=81 per (b,n) row, write transposed [B,C,N]
// ---------------------------------------------------------------------------
__global__ __launch_bounds__(1024) void softmax_T_kernel(const float* __restrict__ conf) {
    __shared__ float tile[32][81];
    int b    = blockIdx.y;
    int n0   = blockIdx.x * 32;
    int warp = threadIdx.x >> 5;
    int lane = threadIdx.x & 31;
    int n    = n0 + warp;

    if (n < N_) {
        const float* row = conf + ((size_t)(b * N_ + n)) * C_;
        float v0 = row[lane];
        float v1 = (lane + 32 < C_) ? row[lane + 32] : -1e30f;
        float v2 = (lane + 64 < C_) ? row[lane + 64] : -1e30f;
        float m = fmaxf(v0, fmaxf(v1, v2));
        #pragma unroll
        for (int o = 16; o; o >>= 1) m = fmaxf(m, __shfl_xor_sync(0xFFFFFFFFu, m, o));
        float e0 = exp_rn(__fsub_rn(v0, m));
        float e1 = (lane + 32 < C_) ? exp_rn(__fsub_rn(v1, m)) : 0.0f;
        float e2 = (lane + 64 < C_) ? exp_rn(__fsub_rn(v2, m)) : 0.0f;
        float s = __fadd_rn(__fadd_rn(e0, e1), e2);
        #pragma unroll
        for (int o = 16; o; o >>= 1) s = __fadd_rn(s, __shfl_xor_sync(0xFFFFFFFFu, s, o));
        float inv = __fdiv_rn(1.0f, s);
        tile[warp][lane] = __fmul_rn(e0, inv);
        if (lane + 32 < C_) tile[warp][lane + 32] = __fmul_rn(e1, inv);
        if (lane + 64 < C_) tile[warp][lane + 64] = __fmul_rn(e2, inv);
    }
    __syncthreads();

    for (int idx = threadIdx.x; idx < 32 * C_; idx += 1024) {
        int c  = idx >> 5;
        int nn = idx & 31;
        int ng = n0 + nn;
        if (ng < N_)
            g_probsT[((size_t)b * C_ + c) * N_ + ng] = tile[nn][c];
    }
}

// ---------------------------------------------------------------------------
// Kernel 2: decode boxes — must stay bitwise-stable (iou decisions depend on it)
// ---------------------------------------------------------------------------
__global__ void decode_kernel(const float* __restrict__ loc,
                              const float* __restrict__ anchors) {
    int i = blockIdx.x * blockDim.x + threadIdx.x;
    if (i >= B_ * N_) return;
    int n = i % N_;
    float4 l = ((const float4*)loc)[i];
    float4 a = ((const float4*)anchors)[n];
    float cx = __fadd_rn(a.x, __fmul_rn(__fmul_rn(l.x, 0.1f), a.z));
    float cy = __fadd_rn(a.y, __fmul_rn(__fmul_rn(l.y, 0.1f), a.w));
    float w  = __fmul_rn(a.z, exp_rn(__fmul_rn(l.z, 0.2f)));
    float h  = __fmul_rn(a.w, exp_rn(__fmul_rn(l.w, 0.2f)));
    float hw = __fmul_rn(w, 0.5f);
    float hh = __fmul_rn(h, 0.5f);
    g_boxes[i] = make_float4(__fsub_rn(cx, hw), __fsub_rn(cy, hh),
                             __fadd_rn(cx, hw), __fadd_rn(cy, hh));
}

// ---------------------------------------------------------------------------
// Kernel 3: per-(b, class!=0) top-200 + IoU + sequential NMS + output
// ---------------------------------------------------------------------------
__global__ __launch_bounds__(256, 8) void nms_kernel(float* __restrict__ out) {
    __shared__ unsigned long long cand[2048];   // aliases hist in early phases
    __shared__ unsigned spart[256];
    __shared__ float4   sbox [TOPK_];
    __shared__ float    svals[TOPK_];
    __shared__ float    sarea[TOPK_];
    __shared__ unsigned smask[TOPK_ * 7];
    __shared__ unsigned skeep[7];
    __shared__ int      sB1, sC1, sB2, sCount;

    unsigned* hist = (unsigned*)cand;

    int task = blockIdx.x;
    int b    = task / (C_ - 1);
    int cls  = task % (C_ - 1) + 1;
    int t    = threadIdx.x;

    const float4* prow4 = (const float4*)(g_probsT + ((size_t)b * C_ + cls) * N_);

    if (t < 7) skeep[t] = 0;
    if (t == 0) sCount = 0;

    // ============ LEVEL 1: histogram on float bits[30:20] ============
    for (int i = t; i < 2048; i += 256) hist[i] = 0;
    __syncthreads();
    for (int i = t; i < NV4_; i += 256) {
        float4 p = prow4[i];
        atomicAdd(&hist[__float_as_uint(p.x) >> 20], 1u);
        atomicAdd(&hist[__float_as_uint(p.y) >> 20], 1u);
        atomicAdd(&hist[__float_as_uint(p.z) >> 20], 1u);
        atomicAdd(&hist[__float_as_uint(p.w) >> 20], 1u);
    }
    __syncthreads();

    // parallel cutoff: suffix-scan of 256 chunk sums, crossing thread refines
    {
        unsigned my = 0;
        #pragma unroll
        for (int q = 0; q < 8; q++) my += hist[t * 8 + q];
        spart[t] = my;
        __syncthreads();
        #pragma unroll
        for (int off = 1; off < 256; off <<= 1) {
            unsigned v = (t + off < 256) ? spart[t + off] : 0u;
            __syncthreads();
            spart[t] += v;
            __syncthreads();
        }
        unsigned incl = spart[t], excl = incl - my;
        if (excl < TOPK_ && TOPK_ <= incl) {        // exactly one thread
            int acc = (int)excl;
            for (int bin = t * 8 + 7; bin >= t * 8; bin--) {
                int h = (int)hist[bin];
                if (acc + h >= TOPK_) { sB1 = bin; sC1 = acc; break; }
                acc += h;
            }
        }
    }
    __syncthreads();
    unsigned b1 = (unsigned)sB1;
    int need2 = TOPK_ - sC1;                        // >= 1

    // ============ LEVEL 2: sub-histogram on bits[19:9] within bin b1 ============
    for (int i = t; i < 2048; i += 256) hist[i] = 0;
    __syncthreads();
    for (int i = t; i < NV4_; i += 256) {
        float4 p = prow4[i];
        unsigned bx = __float_as_uint(p.x), by = __float_as_uint(p.y);
        unsigned bz = __float_as_uint(p.z), bw = __float_as_uint(p.w);
        if ((bx >> 20) == b1) atomicAdd(&hist[(bx >> 9) & 0x7FF], 1u);
        if ((by >> 20) == b1) atomicAdd(&hist[(by >> 9) & 0x7FF], 1u);
        if ((bz >> 20) == b1) atomicAdd(&hist[(bz >> 9) & 0x7FF], 1u);
        if ((bw >> 20) == b1) atomicAdd(&hist[(bw >> 9) & 0x7FF], 1u);
    }
    __syncthreads();
    {
        unsigned my = 0;
        #pragma unroll
        for (int q = 0; q < 8; q++) my += hist[t * 8 + q];
        spart[t] = my;
        __syncthreads();
        #pragma unroll
        for (int off = 1; off < 256; off <<= 1) {
            unsigned v = (t + off < 256) ? spart[t + off] : 0u;
            __syncthreads();
            spart[t] += v;
            __syncthreads();
        }
        unsigned incl = spart[t], excl = incl - my;
        if ((int)excl < need2 && need2 <= (int)incl) {
            int acc = (int)excl;
            for (int bin = t * 8 + 7; bin >= t * 8; bin--) {
                int h = (int)hist[bin];
                if (acc + h >= need2) { sB2 = bin; break; }
                acc += h;
            }
        }
    }
    __syncthreads();
    unsigned b2 = (unsigned)sB2;

    // ============ Collect candidates: M ~= 200 + O(1) ============
    // key = valbits<<32 | ~index  (desc value, asc index — matches lax.top_k)
    for (int i = t; i < NV4_; i += 256) {
        float4 p = prow4[i];
        unsigned bits[4] = {__float_as_uint(p.x), __float_as_uint(p.y),
                            __float_as_uint(p.z), __float_as_uint(p.w)};
        #pragma unroll
        for (int k = 0; k < 4; k++) {
            unsigned bin = bits[k] >> 20;
            if (bin > b1 || (bin == b1 && ((bits[k] >> 9) & 0x7FF) >= b2)) {
                int pos = atomicAdd(&sCount, 1);
                if (pos < 2048)
                    cand[pos] = ((unsigned long long)bits[k] << 32)
                              | (unsigned)(0xFFFFFFFFu - (unsigned)(4 * i + k));
            }
        }
    }
    __syncthreads();
    int M = sCount; if (M > 2048) M = 2048;

    // ============ Rank-by-count selection (keys unique -> exact ranks) ============
    for (int i = t; i < M; i += 256) {
        unsigned long long key = cand[i];
        int r = 0;
        for (int j = 0; j < M; j++) r += (cand[j] > key);   // lockstep j -> LDS broadcast
        if (r < TOPK_) {
            float v = __uint_as_float((unsigned)(key >> 32));
            unsigned n = 0xFFFFFFFFu - (unsigned)key;
            svals[r] = v;
            float4 bx = g_boxes[(size_t)b * N_ + n];
            sbox[r] = bx;
            sarea[r] = __fmul_rn(__fsub_rn(bx.z, bx.x), __fsub_rn(bx.w, bx.y));
            if (v > CONF_) atomicOr(&skeep[r >> 5], 1u << (r & 31));
        }
    }
    __syncthreads();

    // ============ Suppression bitmask: bit j of smask[i][w] = iou(i,j)>thr, j>i ====
    for (int unit = t; unit < TOPK_ * 7; unit += 256) {
        int i = unit / 7, w = unit % 7;
        float4 bi = sbox[i];
        float  ai = sarea[i];
        unsigned word = 0;
        int j0 = w * 32;
        #pragma unroll 4
        for (int jj = 0; jj < 32; jj++) {
            int j = j0 + jj;
            if (j < TOPK_ && j > i) {
                float4 bj = sbox[j];
                float lx = fmaxf(bi.x, bj.x), ly = fmaxf(bi.y, bj.y);
                float rx = fminf(bi.z, bj.z), ry = fminf(bi.w, bj.w);
                float iw = fmaxf(__fsub_rn(rx, lx), 0.0f);
                float ih = fmaxf(__fsub_rn(ry, ly), 0.0f);
                float inter = __fmul_rn(iw, ih);
                float uni = __fsub_rn(__fadd_rn(ai, sarea[j]), inter);
                float iou = __fdiv_rn(inter, fmaxf(uni, 1e-12f));
                if (iou > NMS_) word |= (1u << jj);
            }
        }
        smask[i * 7 + w] = word;
    }
    __syncthreads();

    // ============ Sequential NMS (exact scan semantics), ffs-skip suppressed ====
    if (t == 0) {
        unsigned kw[7];
        #pragma unroll
        for (int w = 0; w < 7; w++) kw[w] = skeep[w];
        for (int w = 0; w < 7; w++) {
            unsigned m = kw[w];
            while (m) {
                int bit = __ffs(m) - 1;
                int i = w * 32 + bit;
                #pragma unroll
                for (int w2 = 0; w2 < 7; w2++)
                    if (w2 >= w) kw[w2] &= ~smask[i * 7 + w2];
                m = kw[w] & (0xFFFFFFFEu << bit);
            }
        }
        #pragma unroll
        for (int w = 0; w < 7; w++) skeep[w] = kw[w];
    }
    __syncthreads();

    // ============ Output [200,5] rows ============
    if (t < TOPK_) {
        bool kp = (skeep[t >> 5] >> (t & 31)) & 1u;
        float* o = out + (((size_t)b * C_ + cls) * TOPK_ + t) * 5;
        float4 bx = sbox[t];
        o[0] = kp ? svals[t] : 0.0f;
        o[1] = kp ? bx.x : 0.0f;
        o[2] = kp ? bx.y : 0.0f;
        o[3] = kp ? bx.z : 0.0f;
        o[4] = kp ? bx.w : 0.0f;
    }
}

// ---------------------------------------------------------------------------
extern "C" void kernel_launch(void* const* d_in, const int* in_sizes, int n_in,
                              void* d_out, int out_size) {
    const float* loc     = (const float*)d_in[0];   // [B,N,4]
    const float* conf    = (const float*)d_in[1];   // [B,N,C]
    const float* anchors = (const float*)d_in[2];   // [N,4]
    float* out = (float*)d_out;                     // [B,C,200,5]

    cudaMemsetAsync(out, 0, (size_t)out_size * sizeof(float), 0);

    dim3 g1((N_ + 31) / 32, B_);
    softmax_T_kernel<<<g1, 1024>>>(conf);

    int tot = B_ * N_;
    decode_kernel<<<(tot + 255) / 256, 256>>>(loc, anchors);

    nms_kernel<<<B_ * (C_ - 1), 256>>>(out);
}

// round 5
// speedup vs baseline: 1.4304x; 1.2280x over previous
#include <cuda_runtime.h>
#include <cuda_bf16.h>
#include <cstdint>

#define B_ 16
#define N_ 8732
#define C_ 81
#define NV4_ 2183            // N_/4, exact
#define ITER1_ 9             // ceil(NV4_/256)
#define TOPK_ 200
#define CONF_ 0.01f
#define NMS_ 0.45f

__device__ float  g_probsT[B_ * C_ * N_];   // [B, C, N] softmax probs, transposed
__device__ float4 g_boxes [B_ * N_];        // [B, N] decoded xyxy

// ---------------------------------------------------------------------------
// Bitwise replica of libdevice __nv_expf — immune to fast-math / contraction.
// ---------------------------------------------------------------------------
__device__ __forceinline__ float exp_rn(float a) {
    float f, r, j, s, t;
    int i, ia;
    j = fmaf(1.442695f, a, 12582912.f);
    j = __fsub_rn(j, 12582912.f);
    f = fmaf(j, -6.93145752e-1f, a);
    f = fmaf(j, -1.42860677e-6f, f);
    i = (int)j;
    r =         1.37805939e-3f;
    r = fmaf(r, f, 8.37312452e-3f);
    r = fmaf(r, f, 4.16695364e-2f);
    r = fmaf(r, f, 1.66664720e-1f);
    r = fmaf(r, f, 4.99999851e-1f);
    r = fmaf(r, f, 1.00000000e+0f);
    r = fmaf(r, f, 1.00000000e+0f);
    ia = (i > 0) ? 0 : 0x83000000;
    s = __int_as_float(0x7f000000 + ia);
    t = __int_as_float((i << 23) - ia);
    r = __fmul_rn(r, s);
    r = __fmul_rn(r, t);
    if (fabsf(a) >= 104.0f) r = (a > 0.0f) ? __int_as_float(0x7f800000) : 0.0f;
    return r;
}

// ---------------------------------------------------------------------------
// Kernel 1: softmax over C=81 per (b,n) row, write transposed [B,C,N]
// (bitwise-stable vs reference — do not perturb)
// ---------------------------------------------------------------------------
__global__ __launch_bounds__(1024) void softmax_T_kernel(const float* __restrict__ conf) {
    __shared__ float tile[32][81];
    int b    = blockIdx.y;
    int n0   = blockIdx.x * 32;
    int warp = threadIdx.x >> 5;
    int lane = threadIdx.x & 31;
    int n    = n0 + warp;

    if (n < N_) {
        const float* row = conf + ((size_t)(b * N_ + n)) * C_;
        float v0 = row[lane];
        float v1 = (lane + 32 < C_) ? row[lane + 32] : -1e30f;
        float v2 = (lane + 64 < C_) ? row[lane + 64] : -1e30f;
        float m = fmaxf(v0, fmaxf(v1, v2));
        #pragma unroll
        for (int o = 16; o; o >>= 1) m = fmaxf(m, __shfl_xor_sync(0xFFFFFFFFu, m, o));
        float e0 = exp_rn(__fsub_rn(v0, m));
        float e1 = (lane + 32 < C_) ? exp_rn(__fsub_rn(v1, m)) : 0.0f;
        float e2 = (lane + 64 < C_) ? exp_rn(__fsub_rn(v2, m)) : 0.0f;
        float s = __fadd_rn(__fadd_rn(e0, e1), e2);
        #pragma unroll
        for (int o = 16; o; o >>= 1) s = __fadd_rn(s, __shfl_xor_sync(0xFFFFFFFFu, s, o));
        float inv = __fdiv_rn(1.0f, s);
        tile[warp][lane] = __fmul_rn(e0, inv);
        if (lane + 32 < C_) tile[warp][lane + 32] = __fmul_rn(e1, inv);
        if (lane + 64 < C_) tile[warp][lane + 64] = __fmul_rn(e2, inv);
    }
    __syncthreads();

    for (int idx = threadIdx.x; idx < 32 * C_; idx += 1024) {
        int c  = idx >> 5;
        int nn = idx & 31;
        int ng = n0 + nn;
        if (ng < N_)
            g_probsT[((size_t)b * C_ + c) * N_ + ng] = tile[nn][c];
    }
}

// ---------------------------------------------------------------------------
// Kernel 2: decode boxes — bitwise-stable (iou decisions depend on it)
// ---------------------------------------------------------------------------
__global__ void decode_kernel(const float* __restrict__ loc,
                              const float* __restrict__ anchors) {
    int i = blockIdx.x * blockDim.x + threadIdx.x;
    if (i >= B_ * N_) return;
    int n = i % N_;
    float4 l = ((const float4*)loc)[i];
    float4 a = ((const float4*)anchors)[n];
    float cx = __fadd_rn(a.x, __fmul_rn(__fmul_rn(l.x, 0.1f), a.z));
    float cy = __fadd_rn(a.y, __fmul_rn(__fmul_rn(l.y, 0.1f), a.w));
    float w  = __fmul_rn(a.z, exp_rn(__fmul_rn(l.z, 0.2f)));
    float h  = __fmul_rn(a.w, exp_rn(__fmul_rn(l.w, 0.2f)));
    float hw = __fmul_rn(w, 0.5f);
    float hh = __fmul_rn(h, 0.5f);
    g_boxes[i] = make_float4(__fsub_rn(cx, hw), __fsub_rn(cy, hh),
                             __fadd_rn(cx, hw), __fadd_rn(cy, hh));
}

// ---------------------------------------------------------------------------
// Kernel 3: per-(b, class!=0) top-200 + IoU + sequential NMS + output
// ---------------------------------------------------------------------------
__global__ __launch_bounds__(256, 8) void nms_kernel(float* __restrict__ out) {
    __shared__ unsigned long long cand[2048];   // 16KB; aliases hist2 early
    __shared__ unsigned hist1[256];             // level-1: exponent bins
    __shared__ unsigned spart[256];
    __shared__ float4   sbox [TOPK_];
    __shared__ float    svals[TOPK_];
    __shared__ float    sarea[TOPK_];
    __shared__ unsigned smask[TOPK_ * 7];
    __shared__ unsigned skeep[7];
    __shared__ int      sB1, sC1, sB2, sCount;

    unsigned* hist2 = (unsigned*)cand;          // level-2: 2048 mantissa bins

    int task = blockIdx.x;
    int b    = task / (C_ - 1);
    int cls  = task % (C_ - 1) + 1;
    int t    = threadIdx.x;
    int lane = t & 31;

    const float4* prow4 = (const float4*)(g_probsT + ((size_t)b * C_ + cls) * N_);

    if (t < 7) skeep[t] = 0;
    if (t == 0) sCount = 0;
    hist1[t] = 0;
    __syncthreads();

    // ============ LEVEL 1: exponent histogram (bits>>23), warp-aggregated ======
    // Uniform trip count so __match_any_sync can use the full mask.
    for (int it = 0; it < ITER1_; it++) {
        int i = t + it * 256;
        bool valid = (i < NV4_);
        float4 p = valid ? prow4[i] : make_float4(0.f, 0.f, 0.f, 0.f);
        unsigned bb[4] = {__float_as_uint(p.x), __float_as_uint(p.y),
                          __float_as_uint(p.z), __float_as_uint(p.w)};
        #pragma unroll
        for (int k = 0; k < 4; k++) {
            unsigned bin = valid ? (bb[k] >> 23) : 0x1FFu;   // probs in [0,1): bin<=126
            unsigned m = __match_any_sync(0xFFFFFFFFu, bin);
            if (valid && lane == (__ffs(m) - 1))
                atomicAdd(&hist1[bin], (unsigned)__popc(m));
        }
    }
    __syncthreads();

    // cutoff over 256 exponent bins: one bin per thread, suffix scan
    {
        unsigned my = hist1[t];
        spart[t] = my;
        __syncthreads();
        #pragma unroll
        for (int off = 1; off < 256; off <<= 1) {
            unsigned v = (t + off < 256) ? spart[t + off] : 0u;
            __syncthreads();
            spart[t] += v;
            __syncthreads();
        }
        unsigned incl = spart[t], excl = incl - my;
        if (excl < TOPK_ && TOPK_ <= incl) { sB1 = t; sC1 = (int)excl; }
    }
    __syncthreads();
    unsigned b1 = (unsigned)sB1;
    int need2 = TOPK_ - sC1;                    // in [1,200]

    // ============ LEVEL 2: mantissa bits[22:12] within exponent b1 =============
    for (int i = t; i < 2048; i += 256) hist2[i] = 0;
    __syncthreads();
    for (int it = 0; it < ITER1_; it++) {
        int i = t + it * 256;
        bool valid = (i < NV4_);
        float4 p = valid ? prow4[i] : make_float4(0.f, 0.f, 0.f, 0.f);
        unsigned bb[4] = {__float_as_uint(p.x), __float_as_uint(p.y),
                          __float_as_uint(p.z), __float_as_uint(p.w)};
        #pragma unroll
        for (int k = 0; k < 4; k++) {
            bool v2 = valid && ((bb[k] >> 23) == b1);
            unsigned bin = v2 ? ((bb[k] >> 12) & 0x7FFu) : 0x8000u;
            unsigned m = __match_any_sync(0xFFFFFFFFu, bin);
            if (v2 && lane == (__ffs(m) - 1))
                atomicAdd(&hist2[bin], (unsigned)__popc(m));
        }
    }
    __syncthreads();
    {
        unsigned my = 0;
        #pragma unroll
        for (int q = 0; q < 8; q++) my += hist2[t * 8 + q];
        spart[t] = my;
        __syncthreads();
        #pragma unroll
        for (int off = 1; off < 256; off <<= 1) {
            unsigned v = (t + off < 256) ? spart[t + off] : 0u;
            __syncthreads();
            spart[t] += v;
            __syncthreads();
        }
        unsigned incl = spart[t], excl = incl - my;
        if ((int)excl < need2 && need2 <= (int)incl) {
            int acc = (int)excl;
            for (int bin = t * 8 + 7; bin >= t * 8; bin--) {
                int h = (int)hist2[bin];
                if (acc + h >= need2) { sB2 = bin; break; }
                acc += h;
            }
        }
    }
    __syncthreads();
    unsigned b2 = (unsigned)sB2;

    // ============ Collect candidates: M ≈ 200 + O(1) ============
    // key = valbits<<32 | ~index  (desc value, asc index — matches lax.top_k)
    for (int i = t; i < NV4_; i += 256) {
        float4 p = prow4[i];
        unsigned bits[4] = {__float_as_uint(p.x), __float_as_uint(p.y),
                            __float_as_uint(p.z), __float_as_uint(p.w)};
        #pragma unroll
        for (int k = 0; k < 4; k++) {
            unsigned e = bits[k] >> 23;
            if (e > b1 || (e == b1 && ((bits[k] >> 12) & 0x7FFu) >= b2)) {
                int pos = atomicAdd(&sCount, 1);
                if (pos < 2048)
                    cand[pos] = ((unsigned long long)bits[k] << 32)
                              | (unsigned)(0xFFFFFFFFu - (unsigned)(4 * i + k));
            }
        }
    }
    __syncthreads();
    int M = sCount; if (M > 2048) M = 2048;

    // ============ Rank-by-count selection (keys unique -> exact ranks) ========
    for (int i = t; i < M; i += 256) {
        unsigned long long key = cand[i];
        int r = 0;
        for (int j = 0; j < M; j++) r += (cand[j] > key);   // LDS broadcast
        if (r < TOPK_) {
            float v = __uint_as_float((unsigned)(key >> 32));
            unsigned n = 0xFFFFFFFFu - (unsigned)key;
            svals[r] = v;
            float4 bx = g_boxes[(size_t)b * N_ + n];
            sbox[r] = bx;
            sarea[r] = __fmul_rn(__fsub_rn(bx.z, bx.x), __fsub_rn(bx.w, bx.y));
            if (v > CONF_) atomicOr(&skeep[r >> 5], 1u << (r & 31));
        }
    }
    __syncthreads();

    // ============ IoU: thread t owns row i=t; lockstep j -> LDS broadcast =====
    // Division-free except inside a +/-2e-5 guard band (then exact __fdiv_rn).
    if (t < TOPK_) {
        float4 bi = sbox[t];
        float  ai = sarea[t];
        unsigned words[7];
        #pragma unroll
        for (int w = 0; w < 7; w++) words[w] = 0;
        for (int j = 0; j < TOPK_; j++) {
            float4 bj = sbox[j];
            float  aj = sarea[j];
            float lx = fmaxf(bi.x, bj.x), ly = fmaxf(bi.y, bj.y);
            float rx = fminf(bi.z, bj.z), ry = fminf(bi.w, bj.w);
            float iw = fmaxf(__fsub_rn(rx, lx), 0.0f);
            float ih = fmaxf(__fsub_rn(ry, ly), 0.0f);
            float inter = __fmul_rn(iw, ih);
            bool sup = false;
            if (inter > 0.0f) {
                float uni = __fsub_rn(__fadd_rn(ai, aj), inter);
                float r45 = __fmul_rn(NMS_, uni);
                if (uni >= 1e-10f) {
                    if (inter > __fmul_rn(r45, 1.00002f)) sup = true;
                    else if (inter >= __fmul_rn(r45, 0.99998f))
                        sup = (__fdiv_rn(inter, fmaxf(uni, 1e-12f)) > NMS_);
                } else {
                    sup = (__fdiv_rn(inter, fmaxf(uni, 1e-12f)) > NMS_);
                }
            }
            if (sup) words[j >> 5] |= (1u << (j & 31));
        }
        // triangle mask: keep only j > t
        int iw_ = t >> 5;
        #pragma unroll
        for (int w = 0; w < 7; w++) {
            unsigned wd = words[w];
            if (w < iw_) wd = 0;
            if (w == iw_) wd &= (0xFFFFFFFEu << (t & 31));
            smask[t * 7 + w] = wd;
        }
    }
    __syncthreads();

    // ============ Sequential NMS (exact scan semantics), ffs-skip =============
    if (t == 0) {
        unsigned kw[7];
        #pragma unroll
        for (int w = 0; w < 7; w++) kw[w] = skeep[w];
        for (int w = 0; w < 7; w++) {
            unsigned m = kw[w];
            while (m) {
                int bit = __ffs(m) - 1;
                int i = w * 32 + bit;
                #pragma unroll
                for (int w2 = 0; w2 < 7; w2++)
                    if (w2 >= w) kw[w2] &= ~smask[i * 7 + w2];
                m = kw[w] & (0xFFFFFFFEu << bit);
            }
        }
        #pragma unroll
        for (int w = 0; w < 7; w++) skeep[w] = kw[w];
    }
    __syncthreads();

    // ============ Output [200,5] rows ============
    if (t < TOPK_) {
        bool kp = (skeep[t >> 5] >> (t & 31)) & 1u;
        float* o = out + (((size_t)b * C_ + cls) * TOPK_ + t) * 5;
        float4 bx = sbox[t];
        o[0] = kp ? svals[t] : 0.0f;
        o[1] = kp ? bx.x : 0.0f;
        o[2] = kp ? bx.y : 0.0f;
        o[3] = kp ? bx.z : 0.0f;
        o[4] = kp ? bx.w : 0.0f;
    }
}

// ---------------------------------------------------------------------------
extern "C" void kernel_launch(void* const* d_in, const int* in_sizes, int n_in,
                              void* d_out, int out_size) {
    const float* loc     = (const float*)d_in[0];   // [B,N,4]
    const float* conf    = (const float*)d_in[1];   // [B,N,C]
    const float* anchors = (const float*)d_in[2];   // [N,4]
    float* out = (float*)d_out;                     // [B,C,200,5]

    cudaMemsetAsync(out, 0, (size_t)out_size * sizeof(float), 0);

    dim3 g1((N_ + 31) / 32, B_);
    softmax_T_kernel<<<g1, 1024>>>(conf);

    int tot = B_ * N_;
    decode_kernel<<<(tot + 255) / 256, 256>>>(loc, anchors);

    nms_kernel<<<B_ * (C_ - 1), 256>>>(out);
}